// round 16
// baseline (speedup 1.0000x reference)
#include <cuda_runtime.h>
#include <cuda_fp16.h>
#include <math.h>
#include <stdint.h>

#define B_  4
#define S_  2048
#define D_  1024
#define H_  16
#define HD  64
#define ROWS (B_*S_)        // 8192
#define SCALE 0.125f        // 64^-0.5

// ---------------- scratch (device globals; no allocations) ----------------
__device__ __half g_q[(size_t)B_*H_*S_*HD];     // [B*H, S, 64] half (Q pre-scaled)
__device__ __half g_k[(size_t)B_*H_*S_*HD];
__device__ __half g_v[(size_t)B_*H_*S_*HD];
__device__ __half g_attnh[(size_t)ROWS*D_];     // attention out, half
__device__ __half g_xh[(size_t)ROWS*D_];        // x in half
__device__ __half g_wqkvh[(size_t)D_*3*D_];     // W_qkv half (row-major [K][N])
__device__ __half g_wprojh[(size_t)D_*D_];      // W_proj half

// ---------------- helpers ---------------------------------------------------
__global__ void conv_half(const float* __restrict__ s, __half* __restrict__ d, int n) {
    int i = (blockIdx.x * blockDim.x + threadIdx.x) * 4;
    if (i < n) {
        float4 v = *(const float4*)(s + i);
        __half2* p = (__half2*)(d + i);
        p[0] = __floats2half2_rn(v.x, v.y);
        p[1] = __floats2half2_rn(v.z, v.w);
    }
}

__device__ __forceinline__ void cp16(void* dst, const void* src) {
    uint32_t d = (uint32_t)__cvta_generic_to_shared(dst);
    asm volatile("cp.async.ca.shared.global [%0], [%1], 16;\n" :: "r"(d), "l"(src));
}
#define CP_COMMIT() asm volatile("cp.async.commit_group;\n" ::: "memory")
#define CP_WAIT0()  asm volatile("cp.async.wait_group 0;\n" ::: "memory")

__device__ __forceinline__ void ldsm4(uint32_t r[4], uint32_t a) {
    asm volatile("ldmatrix.sync.aligned.m8n8.x4.shared.b16 {%0,%1,%2,%3}, [%4];"
        : "=r"(r[0]), "=r"(r[1]), "=r"(r[2]), "=r"(r[3]) : "r"(a));
}
__device__ __forceinline__ void ldsm4t(uint32_t r[4], uint32_t a) {
    asm volatile("ldmatrix.sync.aligned.m8n8.x4.trans.shared.b16 {%0,%1,%2,%3}, [%4];"
        : "=r"(r[0]), "=r"(r[1]), "=r"(r[2]), "=r"(r[3]) : "r"(a));
}
__device__ __forceinline__ void mma16816(float d[4], const uint32_t a[4],
                                         const uint32_t b[2], const float c[4]) {
    asm volatile(
        "mma.sync.aligned.m16n8k16.row.col.f32.f16.f16.f32 "
        "{%0,%1,%2,%3}, {%4,%5,%6,%7}, {%8,%9}, {%10,%11,%12,%13};"
        : "=f"(d[0]), "=f"(d[1]), "=f"(d[2]), "=f"(d[3])
        : "r"(a[0]), "r"(a[1]), "r"(a[2]), "r"(a[3]),
          "r"(b[0]), "r"(b[1]),
          "f"(c[0]), "f"(c[1]), "f"(c[2]), "f"(c[3]));
}
__device__ __forceinline__ uint32_t packh2(float a, float b) {
    __half2 h = __floats2half2_rn(a, b);
    return *(uint32_t*)&h;
}

// ---------------- fp16 tensor-core GEMM: C = A[M,K] @ W[K,N] + bias ---------
// 128x256x64 tiles, 2-stage cp.async, 256 threads (8 warps 2x4), warp 64x64.
#define BM 128
#define BN 256
#define BK 64
#define PAH 72     // A pitch in halves (144B row; 4-bank step -> conflict-free)
#define PBH 264    // B pitch in halves (528B row; 4-bank step -> conflict-free)
#define GEMM_SMEM ((2*BM*PAH + 2*BK*PBH) * 2)   // 104448 B

template<int SCATTER>
__global__ void __launch_bounds__(256, 1) gemm_h(
    const __half* __restrict__ A, const __half* __restrict__ W,
    const float* __restrict__ bias, float* __restrict__ C,
    int M, int N, int K)
{
    extern __shared__ __half smh[];
    __half* As[2] = { smh, smh + BM * PAH };
    __half* Bs[2] = { smh + 2 * BM * PAH, smh + 2 * BM * PAH + BK * PBH };
    const uint32_t sbase = (uint32_t)__cvta_generic_to_shared(smh);
    const uint32_t aoff[2] = { 0u, (uint32_t)(BM * PAH * 2) };
    const uint32_t boff[2] = { (uint32_t)(2 * BM * PAH * 2),
                               (uint32_t)(2 * BM * PAH * 2 + BK * PBH * 2) };

    const int tid  = threadIdx.x;
    const int lane = tid & 31;
    const int wid  = tid >> 5;
    const int g    = lane >> 2;
    const int t    = lane & 3;
    const int wm   = (wid & 1) * 64;
    const int wn   = (wid >> 1) * 64;
    const int m0   = blockIdx.y * BM;
    const int n0   = blockIdx.x * BN;

    const int a_row = lane & 15;
    const int a_cg  = (lane >> 4) * 8;
    const int bt_row = lane & 15;
    const int bt_cg  = (lane >> 4) * 8;

    float acc[4][8][4];
    #pragma unroll
    for (int mi = 0; mi < 4; mi++)
        #pragma unroll
        for (int ni = 0; ni < 8; ni++)
            #pragma unroll
            for (int j = 0; j < 4; j++) acc[mi][ni][j] = 0.f;

    auto stage = [&](int s, int k0) {
        #pragma unroll
        for (int p = 0; p < 4; p++) {       // A: 128 rows x 64 halves
            const int idx = p * 256 + tid;
            const int row = idx >> 3;
            const int ch  = (idx & 7) * 8;
            cp16(&As[s][row * PAH + ch], &A[(size_t)(m0 + row) * K + k0 + ch]);
        }
        #pragma unroll
        for (int p = 0; p < 8; p++) {       // B: 64 rows x 256 halves
            const int idx = p * 256 + tid;
            const int row = idx >> 5;
            const int ch  = (idx & 31) * 8;
            cp16(&Bs[s][row * PBH + ch], &W[(size_t)(k0 + row) * N + n0 + ch]);
        }
        CP_COMMIT();
    };

    const int NT = K / BK;
    stage(0, 0);

    for (int it = 0; it < NT; it++) {
        CP_WAIT0();
        __syncthreads();
        if (it + 1 < NT) stage((it + 1) & 1, (it + 1) * BK);

        const uint32_t ab = sbase + aoff[it & 1];
        const uint32_t bb = sbase + boff[it & 1];

        #pragma unroll
        for (int ks = 0; ks < 4; ks++) {
            uint32_t af[4][4], bf[4][4];
            #pragma unroll
            for (int mi = 0; mi < 4; mi++)
                ldsm4(af[mi], ab + (uint32_t)(((wm + mi * 16 + a_row) * PAH
                                               + ks * 16 + a_cg) * 2));
            #pragma unroll
            for (int pr = 0; pr < 4; pr++)
                ldsm4t(bf[pr], bb + (uint32_t)(((ks * 16 + bt_row) * PBH
                                                + wn + pr * 16 + bt_cg) * 2));
            #pragma unroll
            for (int mi = 0; mi < 4; mi++)
                #pragma unroll
                for (int ni = 0; ni < 8; ni++)
                    mma16816(acc[mi][ni], af[mi], &bf[ni >> 1][(ni & 1) * 2],
                             acc[mi][ni]);
        }
    }

    // epilogue
    #pragma unroll
    for (int mi = 0; mi < 4; mi++) {
        const int r0 = m0 + wm + mi * 16 + g;
        #pragma unroll
        for (int ni = 0; ni < 8; ni++) {
            const int c0 = n0 + wn + ni * 8 + 2 * t;
            float v0 = acc[mi][ni][0] + bias[c0];
            float v1 = acc[mi][ni][1] + bias[c0 + 1];
            float v2 = acc[mi][ni][2] + bias[c0];
            float v3 = acc[mi][ni][3] + bias[c0 + 1];
            if (SCATTER) {
                const int sect = c0 >> 10;
                const int rem  = c0 & 1023;
                const int h    = rem >> 6;
                const int dd   = rem & 63;
                __half* dst = (sect == 0) ? g_q : (sect == 1) ? g_k : g_v;
                const float sc = (sect == 0) ? SCALE : 1.f;
                {
                    const int b = r0 >> 11, s = r0 & 2047;
                    *(__half2*)&dst[(((size_t)(b * H_ + h) * S_) + s) * HD + dd] =
                        __floats2half2_rn(v0 * sc, v1 * sc);
                }
                {
                    const int r1 = r0 + 8;
                    const int b = r1 >> 11, s = r1 & 2047;
                    *(__half2*)&dst[(((size_t)(b * H_ + h) * S_) + s) * HD + dd] =
                        __floats2half2_rn(v2 * sc, v3 * sc);
                }
            } else {
                *(float2*)&C[(size_t)r0 * N + c0]       = make_float2(v0, v1);
                *(float2*)&C[(size_t)(r0 + 8) * N + c0] = make_float2(v2, v3);
            }
        }
    }
}

// ---------------- flash attention: 32 q-rows/warp, P in registers -----------
// 256 threads (8 warps); 256 q-rows/CTA; 64-key tiles, 2-stage KV.
#define LKH 72
#define KVBUF (64*LKH)
#define OFF_K0 0
#define OFF_K1 (1*KVBUF)
#define OFF_V0 (2*KVBUF)
#define OFF_V1 (3*KVBUF)
#define ATTN_SMEM ((4*KVBUF) * 2)   // 36864 B

__global__ void __launch_bounds__(256, 1) attn_h()
{
    extern __shared__ __half smh[];
    const uint32_t sbase = (uint32_t)__cvta_generic_to_shared(smh);
    __half* Ks[2] = { smh + OFF_K0, smh + OFF_K1 };
    __half* Vs[2] = { smh + OFF_V0, smh + OFF_V1 };

    const int tid  = threadIdx.x;
    const int lane = tid & 31;
    const int wid  = tid >> 5;
    const int g    = lane >> 2;
    const int t    = lane & 3;
    const int q0   = blockIdx.x * 256;
    const int bh   = blockIdx.y;

    const __half* Qb = g_q + (size_t)bh * S_ * HD;
    const __half* Kb = g_k + (size_t)bh * S_ * HD;
    const __half* Vb = g_v + (size_t)bh * S_ * HD;

    const int a_row  = lane & 15;                        // A-operand (Q)
    const int a_cg   = (lane >> 4) * 8;
    const int bn_row = (lane & 7) + ((lane & 16) >> 1);  // non-trans B (K)
    const int bn_cg  = (lane & 8);
    const int bt_row = lane & 15;                        // trans B (V)
    const int bt_cg  = (lane >> 4) * 8;

    // ---- stage Q (256x64) across all 4 KV buffers, lift to fragments
    #pragma unroll
    for (int p = 0; p < 8; p++) {
        const int idx = p * 256 + tid;
        const int row = idx >> 3;             // 0..255
        const int ch  = (idx & 7) * 8;
        cp16(&smh[(row >> 6) * KVBUF + (row & 63) * LKH + ch],
             &Qb[(size_t)(q0 + row) * HD + ch]);
    }
    CP_COMMIT();
    CP_WAIT0();
    __syncthreads();

    uint32_t qf[2][4][4];                     // 2 row-blocks of 16 per warp
    #pragma unroll
    for (int rb = 0; rb < 2; rb++) {
        const int rblk = wid * 2 + rb;        // 0..15 (m16 block index)
        const uint32_t qb = sbase + (uint32_t)((((rblk >> 2) * KVBUF)
                              + ((rblk & 3) * 16 + a_row) * LKH) * 2);
        #pragma unroll
        for (int kc = 0; kc < 4; kc++)
            ldsm4(qf[rb][kc], qb + (uint32_t)((kc * 16 + a_cg) * 2));
    }
    __syncthreads();

    auto stage_kv = [&](int s, int kb) {
        #pragma unroll
        for (int p = 0; p < 2; p++) {
            const int idx = p * 256 + tid;
            const int row = idx >> 3;         // 0..63
            const int ch  = (idx & 7) * 8;
            cp16(&Ks[s][row * LKH + ch], &Kb[(size_t)(kb + row) * HD + ch]);
            cp16(&Vs[s][row * LKH + ch], &Vb[(size_t)(kb + row) * HD + ch]);
        }
        CP_COMMIT();
    };

    float oacc[2][8][4];
    float m0v[2], m1v[2], l0v[2], l1v[2];
    #pragma unroll
    for (int rb = 0; rb < 2; rb++) {
        m0v[rb] = -INFINITY; m1v[rb] = -INFINITY; l0v[rb] = 0.f; l1v[rb] = 0.f;
        #pragma unroll
        for (int ni = 0; ni < 8; ni++)
            #pragma unroll
            for (int j = 0; j < 4; j++) oacc[rb][ni][j] = 0.f;
    }

    stage_kv(0, 0);

    for (int kt = 0; kt < S_ / 64; kt++) {
        CP_WAIT0();
        __syncthreads();
        if (kt + 1 < S_ / 64) stage_kv((kt + 1) & 1, (kt + 1) * 64);

        const uint32_t kcur = sbase + (uint32_t)(((kt & 1) ? OFF_K1 : OFF_K0) * 2);
        const uint32_t vcur = sbase + (uint32_t)(((kt & 1) ? OFF_V1 : OFF_V0) * 2);

        // ---- S = Q @ K^T (2 row-blocks share each K fragment)
        float sf[2][8][4];
        #pragma unroll
        for (int rb = 0; rb < 2; rb++)
            #pragma unroll
            for (int ni = 0; ni < 8; ni++)
                #pragma unroll
                for (int j = 0; j < 4; j++) sf[rb][ni][j] = 0.f;

        #pragma unroll
        for (int kc = 0; kc < 4; kc++) {
            #pragma unroll
            for (int np = 0; np < 4; np++) {
                uint32_t kf[4];
                ldsm4(kf, kcur + (uint32_t)(((np * 16 + bn_row) * LKH
                                             + kc * 16 + bn_cg) * 2));
                #pragma unroll
                for (int rb = 0; rb < 2; rb++) {
                    mma16816(sf[rb][np * 2    ], qf[rb][kc], &kf[0], sf[rb][np * 2    ]);
                    mma16816(sf[rb][np * 2 + 1], qf[rb][kc], &kf[2], sf[rb][np * 2 + 1]);
                }
            }
        }

        // ---- online softmax + pack P fragments (per row-block)
        uint32_t pf[2][4][4];
        #pragma unroll
        for (int rb = 0; rb < 2; rb++) {
            float mx0 = -INFINITY, mx1 = -INFINITY;
            #pragma unroll
            for (int ni = 0; ni < 8; ni++) {
                mx0 = fmaxf(mx0, fmaxf(sf[rb][ni][0], sf[rb][ni][1]));
                mx1 = fmaxf(mx1, fmaxf(sf[rb][ni][2], sf[rb][ni][3]));
            }
            mx0 = fmaxf(mx0, __shfl_xor_sync(0xffffffffu, mx0, 1));
            mx0 = fmaxf(mx0, __shfl_xor_sync(0xffffffffu, mx0, 2));
            mx1 = fmaxf(mx1, __shfl_xor_sync(0xffffffffu, mx1, 1));
            mx1 = fmaxf(mx1, __shfl_xor_sync(0xffffffffu, mx1, 2));

            const float nm0 = fmaxf(m0v[rb], mx0);
            const float nm1 = fmaxf(m1v[rb], mx1);
            float sum0 = 0.f, sum1 = 0.f;
            #pragma unroll
            for (int ni = 0; ni < 8; ni++) {
                float p0 = __expf(sf[rb][ni][0] - nm0);
                float p1 = __expf(sf[rb][ni][1] - nm0);
                float p2 = __expf(sf[rb][ni][2] - nm1);
                float p3 = __expf(sf[rb][ni][3] - nm1);
                sum0 += p0 + p1; sum1 += p2 + p3;
                pf[rb][ni >> 1][(ni & 1) * 2    ] = packh2(p0, p1);
                pf[rb][ni >> 1][(ni & 1) * 2 + 1] = packh2(p2, p3);
            }
            sum0 += __shfl_xor_sync(0xffffffffu, sum0, 1);
            sum0 += __shfl_xor_sync(0xffffffffu, sum0, 2);
            sum1 += __shfl_xor_sync(0xffffffffu, sum1, 1);
            sum1 += __shfl_xor_sync(0xffffffffu, sum1, 2);

            const float f0 = __expf(m0v[rb] - nm0);
            const float f1 = __expf(m1v[rb] - nm1);
            l0v[rb] = l0v[rb] * f0 + sum0;  m0v[rb] = nm0;
            l1v[rb] = l1v[rb] * f1 + sum1;  m1v[rb] = nm1;
            #pragma unroll
            for (int ni = 0; ni < 8; ni++) {
                oacc[rb][ni][0] *= f0; oacc[rb][ni][1] *= f0;
                oacc[rb][ni][2] *= f1; oacc[rb][ni][3] *= f1;
            }
        }

        // ---- O += P @ V (2 row-blocks share each V fragment)
        #pragma unroll
        for (int kc = 0; kc < 4; kc++) {
            #pragma unroll
            for (int np = 0; np < 4; np++) {
                uint32_t vf[4];
                ldsm4t(vf, vcur + (uint32_t)(((kc * 16 + bt_row) * LKH
                                              + np * 16 + bt_cg) * 2));
                #pragma unroll
                for (int rb = 0; rb < 2; rb++) {
                    mma16816(oacc[rb][np * 2    ], pf[rb][kc], &vf[0], oacc[rb][np * 2    ]);
                    mma16816(oacc[rb][np * 2 + 1], pf[rb][kc], &vf[2], oacc[rb][np * 2 + 1]);
                }
            }
        }
    }

    // ---- epilogue: normalize, write half to g_attnh[b][s][h*64+dd]
    const int b = bh >> 4, h = bh & 15;
    #pragma unroll
    for (int rb = 0; rb < 2; rb++) {
        const int row0 = q0 + wid * 32 + rb * 16 + g;
        const int row1 = row0 + 8;
        const float inv0 = 1.f / l0v[rb], inv1 = 1.f / l1v[rb];
        #pragma unroll
        for (int ni = 0; ni < 8; ni++) {
            const int col = h * HD + ni * 8 + 2 * t;
            *(__half2*)&g_attnh[((size_t)(b * S_ + row0)) * D_ + col] =
                __floats2half2_rn(oacc[rb][ni][0] * inv0, oacc[rb][ni][1] * inv0);
            *(__half2*)&g_attnh[((size_t)(b * S_ + row1)) * D_ + col] =
                __floats2half2_rn(oacc[rb][ni][2] * inv1, oacc[rb][ni][3] * inv1);
        }
    }
}

// ---------------- launch ----------------------------------------------------
extern "C" void kernel_launch(void* const* d_in, const int* in_sizes, int n_in,
                              void* d_out, int out_size)
{
    const float* x      = (const float*)d_in[0];
    const float* W_qkv  = (const float*)d_in[1];
    const float* b_qkv  = (const float*)d_in[2];
    const float* W_proj = (const float*)d_in[3];
    const float* b_proj = (const float*)d_in[4];
    float* out = (float*)d_out;

    cudaFuncSetAttribute(gemm_h<1>, cudaFuncAttributeMaxDynamicSharedMemorySize, GEMM_SMEM);
    cudaFuncSetAttribute(gemm_h<0>, cudaFuncAttributeMaxDynamicSharedMemorySize, GEMM_SMEM);
    cudaFuncSetAttribute(attn_h, cudaFuncAttributeMaxDynamicSharedMemorySize, ATTN_SMEM);

    __half *xh, *wqkvh, *wprojh, *attnh;
    cudaGetSymbolAddress((void**)&xh, g_xh);
    cudaGetSymbolAddress((void**)&wqkvh, g_wqkvh);
    cudaGetSymbolAddress((void**)&wprojh, g_wprojh);
    cudaGetSymbolAddress((void**)&attnh, g_attnh);

    // 0) fp32 -> fp16 converts
    conv_half<<<(ROWS * D_ / 4 + 255) / 256, 256>>>(x, xh, ROWS * D_);
    conv_half<<<(D_ * 3 * D_ / 4 + 255) / 256, 256>>>(W_qkv, wqkvh, D_ * 3 * D_);
    conv_half<<<(D_ * D_ / 4 + 255) / 256, 256>>>(W_proj, wprojh, D_ * D_);

    // 1) QKV GEMM -> scatter half Q(pre-scaled)/K/V in [B,H,S,64]
    gemm_h<1><<<dim3(3 * D_ / BN, ROWS / BM), 256, GEMM_SMEM>>>(
        xh, wqkvh, b_qkv, nullptr, ROWS, 3 * D_, D_);

    // 2) flash attention (256 q-rows per CTA)
    attn_h<<<dim3(S_ / 256, B_ * H_), 256, ATTN_SMEM>>>();

    // 3) output projection (fp32 out)
    gemm_h<0><<<dim3(D_ / BN, ROWS / BM), 256, GEMM_SMEM>>>(
        attnh, wprojh, b_proj, out, ROWS, D_, D_);
}

// round 17
// speedup vs baseline: 1.0718x; 1.0718x over previous
#include <cuda_runtime.h>
#include <cuda_fp16.h>
#include <math.h>
#include <stdint.h>

#define B_  4
#define S_  2048
#define D_  1024
#define H_  16
#define HD  64
#define ROWS (B_*S_)        // 8192
#define SCALE 0.125f        // 64^-0.5
#define QSCALE 0.18033688011112042f   // SCALE * log2(e): scores in log2 domain

// ---------------- scratch (device globals; no allocations) ----------------
__device__ __half g_q[(size_t)B_*H_*S_*HD];     // [B*H, S, 64] half (Q pre-scaled)
__device__ __half g_k[(size_t)B_*H_*S_*HD];
__device__ __half g_v[(size_t)B_*H_*S_*HD];
__device__ __half g_attnh[(size_t)ROWS*D_];     // attention out, half
__device__ __half g_xh[(size_t)ROWS*D_];        // x in half
__device__ __half g_wqkvh[(size_t)D_*3*D_];     // W_qkv half (row-major [K][N])
__device__ __half g_wprojh[(size_t)D_*D_];      // W_proj half

// ---------------- helpers ---------------------------------------------------
__global__ void conv_half(const float* __restrict__ s, __half* __restrict__ d, int n) {
    int i = (blockIdx.x * blockDim.x + threadIdx.x) * 4;
    if (i < n) {
        float4 v = *(const float4*)(s + i);
        __half2* p = (__half2*)(d + i);
        p[0] = __floats2half2_rn(v.x, v.y);
        p[1] = __floats2half2_rn(v.z, v.w);
    }
}

__device__ __forceinline__ void cp16(void* dst, const void* src) {
    uint32_t d = (uint32_t)__cvta_generic_to_shared(dst);
    asm volatile("cp.async.ca.shared.global [%0], [%1], 16;\n" :: "r"(d), "l"(src));
}
#define CP_COMMIT() asm volatile("cp.async.commit_group;\n" ::: "memory")
#define CP_WAIT0()  asm volatile("cp.async.wait_group 0;\n" ::: "memory")

__device__ __forceinline__ void ldsm4(uint32_t r[4], uint32_t a) {
    asm volatile("ldmatrix.sync.aligned.m8n8.x4.shared.b16 {%0,%1,%2,%3}, [%4];"
        : "=r"(r[0]), "=r"(r[1]), "=r"(r[2]), "=r"(r[3]) : "r"(a));
}
__device__ __forceinline__ void ldsm4t(uint32_t r[4], uint32_t a) {
    asm volatile("ldmatrix.sync.aligned.m8n8.x4.trans.shared.b16 {%0,%1,%2,%3}, [%4];"
        : "=r"(r[0]), "=r"(r[1]), "=r"(r[2]), "=r"(r[3]) : "r"(a));
}
__device__ __forceinline__ void mma16816(float d[4], const uint32_t a[4],
                                         const uint32_t b[2], const float c[4]) {
    asm volatile(
        "mma.sync.aligned.m16n8k16.row.col.f32.f16.f16.f32 "
        "{%0,%1,%2,%3}, {%4,%5,%6,%7}, {%8,%9}, {%10,%11,%12,%13};"
        : "=f"(d[0]), "=f"(d[1]), "=f"(d[2]), "=f"(d[3])
        : "r"(a[0]), "r"(a[1]), "r"(a[2]), "r"(a[3]),
          "r"(b[0]), "r"(b[1]),
          "f"(c[0]), "f"(c[1]), "f"(c[2]), "f"(c[3]));
}
// pack two fp32 into half2 (lo = first arg)
__device__ __forceinline__ uint32_t f22h2(float lo, float hi) {
    uint32_t r;
    asm("cvt.rn.f16x2.f32 %0, %1, %2;" : "=r"(r) : "f"(hi), "f"(lo));
    return r;
}
// 2-wide half exp2
__device__ __forceinline__ uint32_t ex2h2(uint32_t x) {
    uint32_t r;
    asm("ex2.approx.f16x2 %0, %1;" : "=r"(r) : "r"(x));
    return r;
}
__device__ __forceinline__ float2 h2f2(uint32_t v) {
    __half2 h = *(__half2*)&v;
    return __half22float2(h);
}

// ---------------- fp16 tensor-core GEMM: C = A[M,K] @ W[K,N] + bias ---------
// 128x128x64 tiles, 2-stage cp.async, 256 threads (8 warps 2x4), warp 64x32.
#define BM 128
#define BN 128
#define BK 64
#define PAH 72     // A pitch in halves (144B row)
#define PBH 136    // B pitch in halves (272B row)
#define GEMM_SMEM ((2*BM*PAH + 2*BK*PBH) * 2)   // 71680 B

template<int SCATTER>
__global__ void __launch_bounds__(256, 2) gemm_h(
    const __half* __restrict__ A, const __half* __restrict__ W,
    const float* __restrict__ bias, float* __restrict__ C,
    int M, int N, int K)
{
    extern __shared__ __half smh[];
    __half* As[2] = { smh, smh + BM * PAH };
    __half* Bs[2] = { smh + 2 * BM * PAH, smh + 2 * BM * PAH + BK * PBH };
    const uint32_t sbase = (uint32_t)__cvta_generic_to_shared(smh);
    const uint32_t aoff[2] = { 0u, (uint32_t)(BM * PAH * 2) };
    const uint32_t boff[2] = { (uint32_t)(2 * BM * PAH * 2),
                               (uint32_t)(2 * BM * PAH * 2 + BK * PBH * 2) };

    const int tid  = threadIdx.x;
    const int lane = tid & 31;
    const int wid  = tid >> 5;
    const int g    = lane >> 2;
    const int t    = lane & 3;
    const int wm   = (wid & 1) * 64;
    const int wn   = (wid >> 1) * 32;
    const int m0   = blockIdx.y * BM;
    const int n0   = blockIdx.x * BN;

    const int a_row = lane & 15;
    const int a_cg  = (lane >> 4) * 8;
    const int bt_row = lane & 15;
    const int bt_cg  = (lane >> 4) * 8;

    float acc[4][4][4];
    #pragma unroll
    for (int mi = 0; mi < 4; mi++)
        #pragma unroll
        for (int ni = 0; ni < 4; ni++)
            #pragma unroll
            for (int j = 0; j < 4; j++) acc[mi][ni][j] = 0.f;

    auto stage = [&](int s, int k0) {
        #pragma unroll
        for (int p = 0; p < 4; p++) {       // A: 128 rows x 64 halves
            const int idx = p * 256 + tid;
            const int row = idx >> 3;
            const int ch  = (idx & 7) * 8;
            cp16(&As[s][row * PAH + ch], &A[(size_t)(m0 + row) * K + k0 + ch]);
        }
        #pragma unroll
        for (int p = 0; p < 4; p++) {       // B: 64 rows x 128 halves
            const int idx = p * 256 + tid;
            const int row = idx >> 4;
            const int ch  = (idx & 15) * 8;
            cp16(&Bs[s][row * PBH + ch], &W[(size_t)(k0 + row) * N + n0 + ch]);
        }
        CP_COMMIT();
    };

    const int NT = K / BK;
    stage(0, 0);

    for (int it = 0; it < NT; it++) {
        CP_WAIT0();
        __syncthreads();
        if (it + 1 < NT) stage((it + 1) & 1, (it + 1) * BK);

        const uint32_t ab = sbase + aoff[it & 1];
        const uint32_t bb = sbase + boff[it & 1];

        #pragma unroll
        for (int ks = 0; ks < 4; ks++) {
            uint32_t af[4][4], bf[2][4];
            #pragma unroll
            for (int mi = 0; mi < 4; mi++)
                ldsm4(af[mi], ab + (uint32_t)(((wm + mi * 16 + a_row) * PAH
                                               + ks * 16 + a_cg) * 2));
            #pragma unroll
            for (int pr = 0; pr < 2; pr++)
                ldsm4t(bf[pr], bb + (uint32_t)(((ks * 16 + bt_row) * PBH
                                                + wn + pr * 16 + bt_cg) * 2));
            #pragma unroll
            for (int mi = 0; mi < 4; mi++)
                #pragma unroll
                for (int ni = 0; ni < 4; ni++)
                    mma16816(acc[mi][ni], af[mi], &bf[ni >> 1][(ni & 1) * 2],
                             acc[mi][ni]);
        }
    }

    // epilogue
    #pragma unroll
    for (int mi = 0; mi < 4; mi++) {
        const int r0 = m0 + wm + mi * 16 + g;
        #pragma unroll
        for (int ni = 0; ni < 4; ni++) {
            const int c0 = n0 + wn + ni * 8 + 2 * t;
            float v0 = acc[mi][ni][0] + bias[c0];
            float v1 = acc[mi][ni][1] + bias[c0 + 1];
            float v2 = acc[mi][ni][2] + bias[c0];
            float v3 = acc[mi][ni][3] + bias[c0 + 1];
            if (SCATTER) {
                const int sect = c0 >> 10;
                const int rem  = c0 & 1023;
                const int h    = rem >> 6;
                const int dd   = rem & 63;
                __half* dst = (sect == 0) ? g_q : (sect == 1) ? g_k : g_v;
                const float sc = (sect == 0) ? QSCALE : 1.f;  // Q in log2 domain
                {
                    const int b = r0 >> 11, s = r0 & 2047;
                    *(__half2*)&dst[(((size_t)(b * H_ + h) * S_) + s) * HD + dd] =
                        __floats2half2_rn(v0 * sc, v1 * sc);
                }
                {
                    const int r1 = r0 + 8;
                    const int b = r1 >> 11, s = r1 & 2047;
                    *(__half2*)&dst[(((size_t)(b * H_ + h) * S_) + s) * HD + dd] =
                        __floats2half2_rn(v2 * sc, v3 * sc);
                }
            } else {
                *(float2*)&C[(size_t)r0 * N + c0]       = make_float2(v0, v1);
                *(float2*)&C[(size_t)(r0 + 8) * N + c0] = make_float2(v2, v3);
            }
        }
    }
}

// ---------------- flash attention (fp16 mma, P in regs, ex2.f16x2 softmax) --
// 256 threads (8 warps); 128 q-rows (16/warp); 64-key tiles, 2-stage KV.
// Scores arrive in log2 domain (Q pre-scaled by SCALE*log2e).
#define LKH 72
#define OFF_K0 0
#define OFF_K1 (64*LKH)
#define OFF_V0 (2*64*LKH)
#define OFF_V1 (3*64*LKH)
#define ATTN_SMEM ((4*64*LKH) * 2)   // 36864 B

__global__ void __launch_bounds__(256, 2) attn_h()
{
    extern __shared__ __half smh[];
    const uint32_t sbase = (uint32_t)__cvta_generic_to_shared(smh);
    __half* Ks[2] = { smh + OFF_K0, smh + OFF_K1 };
    __half* Vs[2] = { smh + OFF_V0, smh + OFF_V1 };

    const int tid  = threadIdx.x;
    const int lane = tid & 31;
    const int wid  = tid >> 5;
    const int g    = lane >> 2;
    const int t    = lane & 3;
    const int q0   = blockIdx.x * 128;
    const int bh   = blockIdx.y;

    const __half* Qb = g_q + (size_t)bh * S_ * HD;
    const __half* Kb = g_k + (size_t)bh * S_ * HD;
    const __half* Vb = g_v + (size_t)bh * S_ * HD;

    const int a_row  = lane & 15;                        // A-operand (Q)
    const int a_cg   = (lane >> 4) * 8;
    const int bn_row = (lane & 7) + ((lane & 16) >> 1);  // non-trans B (K)
    const int bn_cg  = (lane & 8);
    const int bt_row = lane & 15;                        // trans B (V)
    const int bt_cg  = (lane >> 4) * 8;

    // ---- stage Q (128x64) into K buffers, lift to fragments
    #pragma unroll
    for (int p = 0; p < 4; p++) {
        const int idx = p * 256 + tid;
        const int row = idx >> 3;             // 0..127
        const int ch  = (idx & 7) * 8;
        cp16(&smh[(row >> 6) * OFF_K1 + (row & 63) * LKH + ch],
             &Qb[(size_t)(q0 + row) * HD + ch]);
    }
    CP_COMMIT();
    CP_WAIT0();
    __syncthreads();

    uint32_t qf[4][4];
    {
        const uint32_t qb = sbase + (uint32_t)(((wid >> 2) * OFF_K1
                              + ((wid & 3) * 16 + a_row) * LKH) * 2);
        #pragma unroll
        for (int kc = 0; kc < 4; kc++)
            ldsm4(qf[kc], qb + (uint32_t)((kc * 16 + a_cg) * 2));
    }
    __syncthreads();

    auto stage_kv = [&](int s, int kb) {
        #pragma unroll
        for (int p = 0; p < 2; p++) {
            const int idx = p * 256 + tid;
            const int row = idx >> 3;         // 0..63
            const int ch  = (idx & 7) * 8;
            cp16(&Ks[s][row * LKH + ch], &Kb[(size_t)(kb + row) * HD + ch]);
            cp16(&Vs[s][row * LKH + ch], &Vb[(size_t)(kb + row) * HD + ch]);
        }
        CP_COMMIT();
    };

    float oacc[8][4];
    #pragma unroll
    for (int ni = 0; ni < 8; ni++)
        #pragma unroll
        for (int j = 0; j < 4; j++) oacc[ni][j] = 0.f;
    float m0v = -INFINITY, m1v = -INFINITY, l0v = 0.f, l1v = 0.f;

    stage_kv(0, 0);

    for (int kt = 0; kt < S_ / 64; kt++) {
        CP_WAIT0();
        __syncthreads();
        if (kt + 1 < S_ / 64) stage_kv((kt + 1) & 1, (kt + 1) * 64);

        const uint32_t kcur = sbase + (uint32_t)(((kt & 1) ? OFF_K1 : OFF_K0) * 2);
        const uint32_t vcur = sbase + (uint32_t)(((kt & 1) ? OFF_V1 : OFF_V0) * 2);

        // ---- S = Q @ K^T  (scores in log2 domain)
        float sf[8][4];
        #pragma unroll
        for (int ni = 0; ni < 8; ni++)
            #pragma unroll
            for (int j = 0; j < 4; j++) sf[ni][j] = 0.f;

        #pragma unroll
        for (int kc = 0; kc < 4; kc++) {
            #pragma unroll
            for (int np = 0; np < 4; np++) {
                uint32_t kf[4];
                ldsm4(kf, kcur + (uint32_t)(((np * 16 + bn_row) * LKH
                                             + kc * 16 + bn_cg) * 2));
                mma16816(sf[np * 2    ], qf[kc], &kf[0], sf[np * 2    ]);
                mma16816(sf[np * 2 + 1], qf[kc], &kf[2], sf[np * 2 + 1]);
            }
        }

        // ---- online softmax (base-2; rows g, g+8; quads share rows)
        float mx0 = -INFINITY, mx1 = -INFINITY;
        #pragma unroll
        for (int ni = 0; ni < 8; ni++) {
            mx0 = fmaxf(mx0, fmaxf(sf[ni][0], sf[ni][1]));
            mx1 = fmaxf(mx1, fmaxf(sf[ni][2], sf[ni][3]));
        }
        mx0 = fmaxf(mx0, __shfl_xor_sync(0xffffffffu, mx0, 1));
        mx0 = fmaxf(mx0, __shfl_xor_sync(0xffffffffu, mx0, 2));
        mx1 = fmaxf(mx1, __shfl_xor_sync(0xffffffffu, mx1, 1));
        mx1 = fmaxf(mx1, __shfl_xor_sync(0xffffffffu, mx1, 2));

        const float nm0 = fmaxf(m0v, mx0);
        const float nm1 = fmaxf(m1v, mx1);
        const bool nochange = (nm0 == m0v) && (nm1 == m1v);

        float sum0 = 0.f, sum1 = 0.f;
        uint32_t pf[4][4];   // A-operand fragments of P (fp16x2), in registers
        #pragma unroll
        for (int ni = 0; ni < 8; ni++) {
            // y = s - m; exp2 two-at-a-time in fp16
            uint32_t h01 = ex2h2(f22h2(sf[ni][0] - nm0, sf[ni][1] - nm0));
            uint32_t h23 = ex2h2(f22h2(sf[ni][2] - nm1, sf[ni][3] - nm1));
            pf[ni >> 1][(ni & 1) * 2    ] = h01;
            pf[ni >> 1][(ni & 1) * 2 + 1] = h23;
            float2 p01 = h2f2(h01), p23 = h2f2(h23);
            sum0 += p01.x + p01.y;
            sum1 += p23.x + p23.y;
        }
        sum0 += __shfl_xor_sync(0xffffffffu, sum0, 1);
        sum0 += __shfl_xor_sync(0xffffffffu, sum0, 2);
        sum1 += __shfl_xor_sync(0xffffffffu, sum1, 1);
        sum1 += __shfl_xor_sync(0xffffffffu, sum1, 2);

        if (__all_sync(0xffffffffu, nochange)) {
            l0v += sum0;
            l1v += sum1;
        } else {
            const float f0 = exp2f(m0v - nm0);
            const float f1 = exp2f(m1v - nm1);
            l0v = l0v * f0 + sum0;  m0v = nm0;
            l1v = l1v * f1 + sum1;  m1v = nm1;
            #pragma unroll
            for (int ni = 0; ni < 8; ni++) {
                oacc[ni][0] *= f0; oacc[ni][1] *= f0;
                oacc[ni][2] *= f1; oacc[ni][3] *= f1;
            }
        }

        // ---- O += P @ V  (P fragments straight from registers)
        #pragma unroll
        for (int kc = 0; kc < 4; kc++) {
            #pragma unroll
            for (int np = 0; np < 4; np++) {
                uint32_t vf[4];
                ldsm4t(vf, vcur + (uint32_t)(((kc * 16 + bt_row) * LKH
                                              + np * 16 + bt_cg) * 2));
                mma16816(oacc[np * 2    ], pf[kc], &vf[0], oacc[np * 2    ]);
                mma16816(oacc[np * 2 + 1], pf[kc], &vf[2], oacc[np * 2 + 1]);
            }
        }
    }

    // ---- epilogue: normalize, write half to g_attnh[b][s][h*64+dd]
    const int b = bh >> 4, h = bh & 15;
    const int row0 = q0 + wid * 16 + g;
    const int row1 = row0 + 8;
    const float inv0 = 1.f / l0v, inv1 = 1.f / l1v;
    #pragma unroll
    for (int ni = 0; ni < 8; ni++) {
        const int col = h * HD + ni * 8 + 2 * t;
        *(__half2*)&g_attnh[((size_t)(b * S_ + row0)) * D_ + col] =
            __floats2half2_rn(oacc[ni][0] * inv0, oacc[ni][1] * inv0);
        *(__half2*)&g_attnh[((size_t)(b * S_ + row1)) * D_ + col] =
            __floats2half2_rn(oacc[ni][2] * inv1, oacc[ni][3] * inv1);
    }
}

// ---------------- launch ----------------------------------------------------
extern "C" void kernel_launch(void* const* d_in, const int* in_sizes, int n_in,
                              void* d_out, int out_size)
{
    const float* x      = (const float*)d_in[0];
    const float* W_qkv  = (const float*)d_in[1];
    const float* b_qkv  = (const float*)d_in[2];
    const float* W_proj = (const float*)d_in[3];
    const float* b_proj = (const float*)d_in[4];
    float* out = (float*)d_out;

    cudaFuncSetAttribute(gemm_h<1>, cudaFuncAttributeMaxDynamicSharedMemorySize, GEMM_SMEM);
    cudaFuncSetAttribute(gemm_h<0>, cudaFuncAttributeMaxDynamicSharedMemorySize, GEMM_SMEM);
    cudaFuncSetAttribute(attn_h, cudaFuncAttributeMaxDynamicSharedMemorySize, ATTN_SMEM);

    __half *xh, *wqkvh, *wprojh, *attnh;
    cudaGetSymbolAddress((void**)&xh, g_xh);
    cudaGetSymbolAddress((void**)&wqkvh, g_wqkvh);
    cudaGetSymbolAddress((void**)&wprojh, g_wprojh);
    cudaGetSymbolAddress((void**)&attnh, g_attnh);

    // 0) fp32 -> fp16 converts
    conv_half<<<(ROWS * D_ / 4 + 255) / 256, 256>>>(x, xh, ROWS * D_);
    conv_half<<<(D_ * 3 * D_ / 4 + 255) / 256, 256>>>(W_qkv, wqkvh, D_ * 3 * D_);
    conv_half<<<(D_ * D_ / 4 + 255) / 256, 256>>>(W_proj, wprojh, D_ * D_);

    // 1) QKV GEMM -> scatter half Q(log2-prescaled)/K/V in [B,H,S,64]
    gemm_h<1><<<dim3(3 * D_ / BN, ROWS / BM), 256, GEMM_SMEM>>>(
        xh, wqkvh, b_qkv, nullptr, ROWS, 3 * D_, D_);

    // 2) flash attention (P register-resident, f16x2 exp2 softmax)
    attn_h<<<dim3(S_ / 128, B_ * H_), 256, ATTN_SMEM>>>();

    // 3) output projection (fp32 out)
    gemm_h<0><<<dim3(D_ / BN, ROWS / BM), 256, GEMM_SMEM>>>(
        attnh, wprojh, b_proj, out, ROWS, D_, D_);
}